// round 1
// baseline (speedup 1.0000x reference)
#include <cuda_runtime.h>
#include <math.h>
#include <float.h>

#define Bb  8
#define Cc  256
#define HH  160
#define WW  160
#define HDs 40
#define WDs 40
#define NT  1600           // HDs*WDs tokens per batch
#define BM  64
#define BNn 64
#define BK  16
#define LDS_PAD 68         // 64 + 4 padding (keeps float4 alignment, kills bank conflicts)

// ---------------- static scratch (allocation-free rule) ----------------
__device__ float g_ds_rgb[Bb*Cc*NT];                    // [B,C,N] downsampled rgb
__device__ float g_ds_ir [Bb*Cc*NT];                    // [B,C,N] downsampled ir
__device__ float g_tok[6][Bb*NT*Cc];                    // q_rgb,k_ir,v_ir,q_ir,k_rgb,v_rgb  [B,N,C]
__device__ float g_attn0[(size_t)Bb*NT*NT];             // attn_rgb  [B,N,N]
__device__ float g_attn1[(size_t)Bb*NT*NT];             // attn_ir   [B,N,N]
__device__ float g_zcat[Bb*NT*2*Cc];                    // [B,N,2C]: [z_rgb' | z_ir']
__device__ float g_pre[3][Bb*NT*Cc];                    // raw h_rgb, h_ir, gate pre-activation
__device__ float g_fused[Bb*Cc*NT];                     // [B,C,N] fused at low res

// ---------------- downsample: exact 2x2 mean of rows/cols {4i+1,4i+2} ----------------
__global__ void ds_kernel(const float* __restrict__ zr, const float* __restrict__ zi) {
    int idx = blockIdx.x * blockDim.x + threadIdx.x;
    if (idx >= Bb*Cc*NT) return;
    int n  = idx % NT;
    int bc = idx / NT;
    int wo = n % WDs, ho = n / WDs;
    int base = bc * (HH*WW) + (4*ho + 1) * WW + (4*wo + 1);
    float r = 0.25f * (zr[base] + zr[base+1] + zr[base+WW] + zr[base+WW+1]);
    float v = 0.25f * (zi[base] + zi[base+1] + zi[base+WW] + zi[base+WW+1]);
    g_ds_rgb[idx] = r;
    g_ds_ir [idx] = v;
}

// ---------------- shared inner product tile: 4x4 micro tile, 16 FFMA / k ----------------
__device__ __forceinline__ void gemm_tile(const float (*As)[LDS_PAD], const float (*Bs)[LDS_PAD],
                                          float acc[4][4], int ty, int tx) {
#pragma unroll
    for (int kk = 0; kk < BK; kk++) {
        float4 a4 = *(const float4*)&As[kk][ty*4];
        float4 b4 = *(const float4*)&Bs[kk][tx*4];
        float ar[4] = {a4.x, a4.y, a4.z, a4.w};
        float br[4] = {b4.x, b4.y, b4.z, b4.w};
#pragma unroll
        for (int i = 0; i < 4; i++)
#pragma unroll
            for (int j = 0; j < 4; j++)
                acc[i][j] = fmaf(ar[i], br[j], acc[i][j]);
    }
}

// ---------------- projections: out[b,n,o] = sum_c ds[b,c,n] * W[o,c] + bias[o] ----------------
__global__ void proj_gemm(
    const float* __restrict__ Wq_rgb, const float* __restrict__ bq_rgb,
    const float* __restrict__ Wk_ir,  const float* __restrict__ bk_ir,
    const float* __restrict__ Wv_ir,  const float* __restrict__ bv_ir,
    const float* __restrict__ Wq_ir,  const float* __restrict__ bq_ir,
    const float* __restrict__ Wk_rgb, const float* __restrict__ bk_rgb,
    const float* __restrict__ Wv_rgb, const float* __restrict__ bv_rgb)
{
    __shared__ float As[BK][LDS_PAD];
    __shared__ float Bs[BK][LDS_PAD];
    int m0 = blockIdx.x * BM, o0 = blockIdx.y * BNn;
    int b = blockIdx.z / 6, p = blockIdx.z % 6;
    const float *A, *Wt, *bias;
    switch (p) {
        case 0: A = g_ds_rgb; Wt = Wq_rgb; bias = bq_rgb; break;
        case 1: A = g_ds_ir;  Wt = Wk_ir;  bias = bk_ir;  break;
        case 2: A = g_ds_ir;  Wt = Wv_ir;  bias = bv_ir;  break;
        case 3: A = g_ds_ir;  Wt = Wq_ir;  bias = bq_ir;  break;
        case 4: A = g_ds_rgb; Wt = Wk_rgb; bias = bk_rgb; break;
        default:A = g_ds_rgb; Wt = Wv_rgb; bias = bv_rgb; break;
    }
    A += b * Cc * NT;
    float* out = g_tok[p] + b * NT * Cc;
    int tid = threadIdx.x;
    int a_k = tid >> 4, a_m = (tid & 15) * 4;     // A: [k,m], m contiguous
    int b_n = tid >> 2, b_k4 = (tid & 3) * 4;     // W: [o,k], k contiguous -> transpose store
    int ty = tid >> 4, tx = tid & 15;
    float acc[4][4] = {};
    for (int k0 = 0; k0 < Cc; k0 += BK) {
        float4 av = *(const float4*)(A + (k0 + a_k) * NT + m0 + a_m);
        *(float4*)&As[a_k][a_m] = av;
        float4 bv = *(const float4*)(Wt + (o0 + b_n) * Cc + k0 + b_k4);
        Bs[b_k4+0][b_n] = bv.x; Bs[b_k4+1][b_n] = bv.y;
        Bs[b_k4+2][b_n] = bv.z; Bs[b_k4+3][b_n] = bv.w;
        __syncthreads();
        gemm_tile(As, Bs, acc, ty, tx);
        __syncthreads();
    }
#pragma unroll
    for (int i = 0; i < 4; i++) {
        int m = m0 + ty*4 + i;
#pragma unroll
        for (int j = 0; j < 4; j++) {
            int o = o0 + tx*4 + j;
            out[m * Cc + o] = acc[i][j] + bias[o];
        }
    }
}

// ---------------- scores: S[m,n] = (q[m,:] . k[n,:]) * 1/16 ----------------
__global__ void scores_gemm() {
    __shared__ float As[BK][LDS_PAD];
    __shared__ float Bs[BK][LDS_PAD];
    int m0 = blockIdx.x * BM, n0 = blockIdx.y * BNn;
    int dir = blockIdx.z >> 3, b = blockIdx.z & 7;
    const float* Aq = g_tok[dir ? 3 : 0] + b * NT * Cc;
    const float* Bk = g_tok[dir ? 4 : 1] + b * NT * Cc;
    float* out = (dir ? g_attn1 : g_attn0) + (size_t)b * NT * NT;
    int tid = threadIdx.x;
    int r = tid >> 2, k4 = (tid & 3) * 4;
    int ty = tid >> 4, tx = tid & 15;
    float acc[4][4] = {};
    for (int k0 = 0; k0 < Cc; k0 += BK) {
        float4 av = *(const float4*)(Aq + (m0 + r) * Cc + k0 + k4);
        As[k4+0][r] = av.x; As[k4+1][r] = av.y; As[k4+2][r] = av.z; As[k4+3][r] = av.w;
        float4 bv = *(const float4*)(Bk + (n0 + r) * Cc + k0 + k4);
        Bs[k4+0][r] = bv.x; Bs[k4+1][r] = bv.y; Bs[k4+2][r] = bv.z; Bs[k4+3][r] = bv.w;
        __syncthreads();
        gemm_tile(As, Bs, acc, ty, tx);
        __syncthreads();
    }
#pragma unroll
    for (int i = 0; i < 4; i++)
#pragma unroll
        for (int j = 0; j < 4; j++)
            out[(size_t)(m0 + ty*4 + i) * NT + n0 + tx*4 + j] = acc[i][j] * 0.0625f;
}

// ---------------- rowwise softmax over N=1600 ----------------
__global__ void softmax_kernel() {
    int row = blockIdx.x;
    int dir = blockIdx.y >> 3, b = blockIdx.y & 7;
    float* p = (dir ? g_attn1 : g_attn0) + (size_t)b * NT * NT + (size_t)row * NT;
    __shared__ float buf[NT];
    __shared__ float red[256];
    int tid = threadIdx.x;
    float m = -FLT_MAX;
    for (int i = tid; i < NT; i += 256) { float v = p[i]; buf[i] = v; m = fmaxf(m, v); }
    red[tid] = m; __syncthreads();
    for (int s = 128; s; s >>= 1) { if (tid < s) red[tid] = fmaxf(red[tid], red[tid+s]); __syncthreads(); }
    m = red[0]; __syncthreads();
    float sum = 0.f;
    for (int i = tid; i < NT; i += 256) { float e = expf(buf[i] - m); buf[i] = e; sum += e; }
    red[tid] = sum; __syncthreads();
    for (int s = 128; s; s >>= 1) { if (tid < s) red[tid] += red[tid+s]; __syncthreads(); }
    float inv = 1.0f / red[0];
    for (int i = tid; i < NT; i += 256) p[i] = buf[i] * inv;
}

// ---------------- attn @ V -> g_zcat (rgb' into cols[0:256), ir' into cols[256:512)) ----------------
__global__ void av_gemm() {
    __shared__ float As[BK][LDS_PAD];
    __shared__ float Bs[BK][LDS_PAD];
    int m0 = blockIdx.x * BM, o0 = blockIdx.y * BNn;
    int dir = blockIdx.z >> 3, b = blockIdx.z & 7;
    const float* P = (dir ? g_attn1 : g_attn0) + (size_t)b * NT * NT;
    const float* V = g_tok[dir ? 5 : 2] + b * NT * Cc;
    float* out = g_zcat + b * NT * 2 * Cc + dir * Cc;
    int tid = threadIdx.x;
    int a_r = tid >> 2, a_k4 = (tid & 3) * 4;
    int bs_k = tid >> 4, bs_n = (tid & 15) * 4;
    int ty = tid >> 4, tx = tid & 15;
    float acc[4][4] = {};
    for (int k0 = 0; k0 < NT; k0 += BK) {
        float4 av = *(const float4*)(P + (size_t)(m0 + a_r) * NT + k0 + a_k4);
        As[a_k4+0][a_r] = av.x; As[a_k4+1][a_r] = av.y;
        As[a_k4+2][a_r] = av.z; As[a_k4+3][a_r] = av.w;
        float4 bv = *(const float4*)(V + (k0 + bs_k) * Cc + o0 + bs_n);
        *(float4*)&Bs[bs_k][bs_n] = bv;
        __syncthreads();
        gemm_tile(As, Bs, acc, ty, tx);
        __syncthreads();
    }
#pragma unroll
    for (int i = 0; i < 4; i++)
#pragma unroll
        for (int j = 0; j < 4; j++)
            out[(m0 + ty*4 + i) * (2*Cc) + o0 + tx*4 + j] = acc[i][j];
}

// ---------------- epilogue GEMMs: h_rgb, h_ir (K=256), gate (K=512) -> raw pre-activation ----------------
__global__ void final_gemm(const float* __restrict__ Wrgb, const float* __restrict__ brgb,
                           const float* __restrict__ Wir,  const float* __restrict__ bir,
                           const float* __restrict__ Wz,   const float* __restrict__ bz) {
    __shared__ float As[BK][LDS_PAD];
    __shared__ float Bs[BK][LDS_PAD];
    int m0 = blockIdx.x * BM, o0 = blockIdx.y * BNn;
    int b = blockIdx.z / 3, jj = blockIdx.z % 3;
    const float* A = g_zcat + b * NT * 2 * Cc + (jj == 1 ? Cc : 0);
    int Kd = (jj == 2) ? 2*Cc : Cc;
    const float* Wt   = (jj == 0) ? Wrgb : ((jj == 1) ? Wir : Wz);
    const float* bias = (jj == 0) ? brgb : ((jj == 1) ? bir : bz);
    float* out = g_pre[jj] + b * NT * Cc;
    int tid = threadIdx.x;
    int a_r = tid >> 2, a_k4 = (tid & 3) * 4;
    int b_n = tid >> 2, b_k4 = (tid & 3) * 4;
    int ty = tid >> 4, tx = tid & 15;
    float acc[4][4] = {};
    for (int k0 = 0; k0 < Kd; k0 += BK) {
        float4 av = *(const float4*)(A + (m0 + a_r) * (2*Cc) + k0 + a_k4);
        As[a_k4+0][a_r] = av.x; As[a_k4+1][a_r] = av.y;
        As[a_k4+2][a_r] = av.z; As[a_k4+3][a_r] = av.w;
        float4 bv = *(const float4*)(Wt + (o0 + b_n) * Kd + k0 + b_k4);
        Bs[b_k4+0][b_n] = bv.x; Bs[b_k4+1][b_n] = bv.y;
        Bs[b_k4+2][b_n] = bv.z; Bs[b_k4+3][b_n] = bv.w;
        __syncthreads();
        gemm_tile(As, Bs, acc, ty, tx);
        __syncthreads();
    }
#pragma unroll
    for (int i = 0; i < 4; i++) {
        int m = m0 + ty*4 + i;
#pragma unroll
        for (int j = 0; j < 4; j++) {
            int o = o0 + tx*4 + j;
            out[m * Cc + o] = acc[i][j] + bias[o];
        }
    }
}

// ---------------- gate fuse + transpose to [B,C,N] ----------------
__global__ void fuse_kernel(const int* __restrict__ time_idx, const float* __restrict__ temb) {
    int idx = blockIdx.x * blockDim.x + threadIdx.x;
    if (idx >= Bb*NT*Cc) return;
    int o = idx % Cc;
    int n = (idx / Cc) % NT;
    int b = idx / (Cc * NT);
    float hr = tanhf(g_pre[0][idx]);
    float hi = tanhf(g_pre[1][idx]);
    float zb = 1.0f / (1.0f + expf(-g_pre[2][idx]));
    float t  = temb[time_idx[b] * Cc + o];
    float z  = 1.0f / (1.0f + expf(-(zb + t)));
    g_fused[b * Cc * NT + o * NT + n] = z * hr + (1.0f - z) * hi;
}

// ---------------- bilinear upsample 40 -> 160 (align_corners=False) ----------------
__global__ void upsample_kernel(float* __restrict__ out) {
    int idx = blockIdx.x * blockDim.x + threadIdx.x;
    if (idx >= Bb*Cc*HH*WW) return;
    int w  = idx % WW;
    int h  = (idx / WW) % HH;
    int bc = idx / (HH * WW);
    float sh = fmaxf(h * 0.25f - 0.375f, 0.0f);
    float sw = fmaxf(w * 0.25f - 0.375f, 0.0f);
    int h0 = (int)sh; float fh = sh - (float)h0; int h1 = min(h0 + 1, HDs - 1);
    int w0 = (int)sw; float fw = sw - (float)w0; int w1 = min(w0 + 1, WDs - 1);
    const float* p = g_fused + bc * NT;
    float v00 = p[h0 * WDs + w0], v01 = p[h0 * WDs + w1];
    float v10 = p[h1 * WDs + w0], v11 = p[h1 * WDs + w1];
    float top = v00 * (1.0f - fw) + v01 * fw;
    float bot = v10 * (1.0f - fw) + v11 * fw;
    out[idx] = top * (1.0f - fh) + bot * fh;
}

extern "C" void kernel_launch(void* const* d_in, const int* in_sizes, int n_in,
                              void* d_out, int out_size) {
    const float* z_rgb  = (const float*)d_in[0];
    const float* z_ir   = (const float*)d_in[1];
    const int*   tidx   = (const int*)  d_in[2];
    const float* Wq_rgb = (const float*)d_in[3],  *bq_rgb = (const float*)d_in[4];
    const float* Wk_ir  = (const float*)d_in[5],  *bk_ir  = (const float*)d_in[6];
    const float* Wv_ir  = (const float*)d_in[7],  *bv_ir  = (const float*)d_in[8];
    const float* Wq_ir  = (const float*)d_in[9],  *bq_ir  = (const float*)d_in[10];
    const float* Wk_rgb = (const float*)d_in[11], *bk_rgb = (const float*)d_in[12];
    const float* Wv_rgb = (const float*)d_in[13], *bv_rgb = (const float*)d_in[14];
    const float* Wrgb   = (const float*)d_in[15], *brgb   = (const float*)d_in[16];
    const float* Wir    = (const float*)d_in[17], *bir    = (const float*)d_in[18];
    const float* Wz     = (const float*)d_in[19], *bz     = (const float*)d_in[20];
    const float* temb   = (const float*)d_in[21];

    ds_kernel<<<(Bb*Cc*NT + 255) / 256, 256>>>(z_rgb, z_ir);
    proj_gemm<<<dim3(25, 4, 48), 256>>>(Wq_rgb, bq_rgb, Wk_ir, bk_ir, Wv_ir, bv_ir,
                                        Wq_ir, bq_ir, Wk_rgb, bk_rgb, Wv_rgb, bv_rgb);
    scores_gemm<<<dim3(25, 25, 16), 256>>>();
    softmax_kernel<<<dim3(NT, 16), 256>>>();
    av_gemm<<<dim3(25, 4, 16), 256>>>();
    final_gemm<<<dim3(25, 4, 24), 256>>>(Wrgb, brgb, Wir, bir, Wz, bz);
    fuse_kernel<<<(Bb*NT*Cc + 255) / 256, 256>>>(tidx, temb);
    upsample_kernel<<<(Bb*Cc*HH*WW + 255) / 256, 256>>>((float*)d_out);
}

// round 2
// speedup vs baseline: 2.8041x; 2.8041x over previous
#include <cuda_runtime.h>
#include <math.h>
#include <float.h>

#define Bb  8
#define Cc  256
#define HH  160
#define WW  160
#define HDs 40
#define WDs 40
#define NT  1600            // tokens per batch
#define MT  (Bb*NT)         // 12800 total tokens
#define PAD 36              // smem row stride in floats (64+pad -> conflict-free frags)

// ---------------- static scratch ----------------
__device__ float g_ds_rgb[MT*Cc];            // [B*N, C] token-major
__device__ float g_ds_ir [MT*Cc];
__device__ float g_tok[6][MT*Cc];            // q_rgb,k_ir,v_ir,q_ir,k_rgb,v_rgb  [B*N, C]
__device__ float g_attn0[(size_t)Bb*NT*NT];  // attn_rgb  [B,N,N]
__device__ float g_attn1[(size_t)Bb*NT*NT];  // attn_ir
__device__ float g_zcat[MT*2*Cc];            // [B*N, 2C]: [z_rgb' | z_ir']
__device__ float g_pre[3][MT*Cc];            // pre-activation h_rgb, h_ir, gate
__device__ float g_fused[Bb*Cc*NT];          // [B,C,N]

// ---------------- helpers ----------------
__device__ __forceinline__ unsigned f2tf(float x) {
    unsigned r; asm("cvt.rna.tf32.f32 %0, %1;" : "=r"(r) : "f"(x)); return r;
}

// ---------------- tf32 tensor-core GEMM: 64x64 block tile, 4 warps ----------------
// A: [64 rows of K] row-major (lda). B: if B_KN: [K rows of 64 cols] (ldb, n contiguous)
//                                     else:     [64 rows of K] (ldb, k contiguous)
// out: 64x64 at (0,0) of given pointer, stride ldo. Computes out = (A.B^T)*scale + bias.
template<bool B_KN, bool HAS_BIAS>
__device__ __forceinline__ void gemm_tile64(
    const float* __restrict__ A, int lda,
    const float* __restrict__ B, int ldb,
    float* __restrict__ out, int ldo,
    const float* __restrict__ bias, float scale, int K)
{
    __shared__ unsigned As[64*PAD];
    __shared__ unsigned Bs[64*PAD];
    const int tid  = threadIdx.x;      // 128 threads
    const int lane = tid & 31, warp = tid >> 5;
    const int wm = (warp >> 1) * 32;   // warp row offset: 0 or 32
    const int wn = (warp & 1) * 32;    // warp col offset: 0 or 32
    const int g  = lane >> 2, tg = lane & 3;

    float acc[2][4][4];
#pragma unroll
    for (int i = 0; i < 2; i++)
#pragma unroll
        for (int j = 0; j < 4; j++)
#pragma unroll
            for (int l = 0; l < 4; l++) acc[i][j][l] = 0.f;

    for (int k0 = 0; k0 < K; k0 += 32) {
        // --- load A tile 64x32 ---
#pragma unroll
        for (int i = 0; i < 4; i++) {
            int idx = tid + i * 128;
            int m = idx >> 3, kg = (idx & 7) * 4;
            float4 v = *(const float4*)(A + (size_t)m * lda + k0 + kg);
            unsigned* p = &As[m * PAD + kg];
            p[0] = f2tf(v.x); p[1] = f2tf(v.y); p[2] = f2tf(v.z); p[3] = f2tf(v.w);
        }
        // --- load B tile into Bs[n][k] ---
        if (!B_KN) {
#pragma unroll
            for (int i = 0; i < 4; i++) {
                int idx = tid + i * 128;
                int n = idx >> 3, kg = (idx & 7) * 4;
                float4 v = *(const float4*)(B + (size_t)n * ldb + k0 + kg);
                unsigned* p = &Bs[n * PAD + kg];
                p[0] = f2tf(v.x); p[1] = f2tf(v.y); p[2] = f2tf(v.z); p[3] = f2tf(v.w);
            }
        } else {
#pragma unroll
            for (int i = 0; i < 4; i++) {
                int idx = tid + i * 128;
                int k = idx >> 4, ng = (idx & 15) * 4;
                float4 v = *(const float4*)(B + (size_t)(k0 + k) * ldb + ng);
                Bs[(ng + 0) * PAD + k] = f2tf(v.x);
                Bs[(ng + 1) * PAD + k] = f2tf(v.y);
                Bs[(ng + 2) * PAD + k] = f2tf(v.z);
                Bs[(ng + 3) * PAD + k] = f2tf(v.w);
            }
        }
        __syncthreads();
        // --- 4 k8 slices ---
#pragma unroll
        for (int s = 0; s < 4; s++) {
            const int kk = s * 8;
            unsigned a[2][4], b[4][2];
#pragma unroll
            for (int mi = 0; mi < 2; mi++) {
                int rm = wm + mi * 16;
                a[mi][0] = As[(rm + g) * PAD + kk + tg];
                a[mi][1] = As[(rm + 8 + g) * PAD + kk + tg];
                a[mi][2] = As[(rm + g) * PAD + kk + tg + 4];
                a[mi][3] = As[(rm + 8 + g) * PAD + kk + tg + 4];
            }
#pragma unroll
            for (int ni = 0; ni < 4; ni++) {
                int rn = wn + ni * 8;
                b[ni][0] = Bs[(rn + g) * PAD + kk + tg];
                b[ni][1] = Bs[(rn + g) * PAD + kk + tg + 4];
            }
#pragma unroll
            for (int mi = 0; mi < 2; mi++)
#pragma unroll
                for (int ni = 0; ni < 4; ni++) {
                    asm volatile(
                        "mma.sync.aligned.m16n8k8.row.col.f32.tf32.tf32.f32 "
                        "{%0,%1,%2,%3}, {%4,%5,%6,%7}, {%8,%9}, {%0,%1,%2,%3};"
                        : "+f"(acc[mi][ni][0]), "+f"(acc[mi][ni][1]),
                          "+f"(acc[mi][ni][2]), "+f"(acc[mi][ni][3])
                        : "r"(a[mi][0]), "r"(a[mi][1]), "r"(a[mi][2]), "r"(a[mi][3]),
                          "r"(b[ni][0]), "r"(b[ni][1]));
                }
        }
        __syncthreads();
    }
    // --- epilogue: scale, bias, store ---
#pragma unroll
    for (int mi = 0; mi < 2; mi++) {
#pragma unroll
        for (int ni = 0; ni < 4; ni++) {
            int col = wn + ni * 8 + 2 * tg;
            float b0 = 0.f, b1 = 0.f;
            if (HAS_BIAS) { b0 = bias[col]; b1 = bias[col + 1]; }
            int r0 = wm + mi * 16 + g;
            float2 v0 = { acc[mi][ni][0] * scale + b0, acc[mi][ni][1] * scale + b1 };
            float2 v1 = { acc[mi][ni][2] * scale + b0, acc[mi][ni][3] * scale + b1 };
            *(float2*)(out + (size_t)r0 * ldo + col) = v0;
            *(float2*)(out + (size_t)(r0 + 8) * ldo + col) = v1;
        }
    }
}

// ---------------- downsample: exact 2x2 mean, write token-major [B*N, C] ----------------
__global__ void ds_kernel(const float* __restrict__ zr, const float* __restrict__ zi) {
    int idx = blockIdx.x * blockDim.x + threadIdx.x;
    if (idx >= MT * Cc) return;
    int c = idx % Cc;
    int rem = idx / Cc;       // b*NT + n
    int n = rem % NT, b = rem / NT;
    int ho = n / WDs, wo = n % WDs;
    int base = ((b * Cc + c) * HH + 4 * ho + 1) * WW + 4 * wo + 1;
    g_ds_rgb[idx] = 0.25f * (zr[base] + zr[base+1] + zr[base+WW] + zr[base+WW+1]);
    g_ds_ir [idx] = 0.25f * (zi[base] + zi[base+1] + zi[base+WW] + zi[base+WW+1]);
}

// ---------------- projections: 6 GEMMs, M=12800, N=256, K=256 ----------------
__global__ void proj_gemm(
    const float* __restrict__ Wq_rgb, const float* __restrict__ bq_rgb,
    const float* __restrict__ Wk_ir,  const float* __restrict__ bk_ir,
    const float* __restrict__ Wv_ir,  const float* __restrict__ bv_ir,
    const float* __restrict__ Wq_ir,  const float* __restrict__ bq_ir,
    const float* __restrict__ Wk_rgb, const float* __restrict__ bk_rgb,
    const float* __restrict__ Wv_rgb, const float* __restrict__ bv_rgb)
{
    int m0 = blockIdx.x * 64, n0 = blockIdx.y * 64, p = blockIdx.z;
    const float *A, *W, *bias;
    switch (p) {
        case 0: A = g_ds_rgb; W = Wq_rgb; bias = bq_rgb; break;
        case 1: A = g_ds_ir;  W = Wk_ir;  bias = bk_ir;  break;
        case 2: A = g_ds_ir;  W = Wv_ir;  bias = bv_ir;  break;
        case 3: A = g_ds_ir;  W = Wq_ir;  bias = bq_ir;  break;
        case 4: A = g_ds_rgb; W = Wk_rgb; bias = bk_rgb; break;
        default:A = g_ds_rgb; W = Wv_rgb; bias = bv_rgb; break;
    }
    gemm_tile64<false, true>(A + (size_t)m0 * Cc, Cc, W + (size_t)n0 * Cc, Cc,
                             g_tok[p] + (size_t)m0 * Cc + n0, Cc, bias + n0, 1.0f, Cc);
}

// ---------------- scores: S = (Q K^T)/16, per (b,dir): 1600x1600x256 ----------------
__global__ void scores_gemm() {
    int m0 = blockIdx.x * 64, n0 = blockIdx.y * 64;
    int dir = blockIdx.z >> 3, b = blockIdx.z & 7;
    const float* Aq = g_tok[dir ? 3 : 0] + (size_t)b * NT * Cc + (size_t)m0 * Cc;
    const float* Bk = g_tok[dir ? 4 : 1] + (size_t)b * NT * Cc + (size_t)n0 * Cc;
    float* out = (dir ? g_attn1 : g_attn0) + (size_t)b * NT * NT + (size_t)m0 * NT + n0;
    gemm_tile64<false, false>(Aq, Cc, Bk, Cc, out, NT, nullptr, 0.0625f, Cc);
}

// ---------------- rowwise softmax over N=1600 ----------------
__global__ void softmax_kernel() {
    int row = blockIdx.x;
    int dir = blockIdx.y >> 3, b = blockIdx.y & 7;
    float* p = (dir ? g_attn1 : g_attn0) + (size_t)b * NT * NT + (size_t)row * NT;
    __shared__ float buf[NT];
    __shared__ float red[256];
    int tid = threadIdx.x;
    float m = -FLT_MAX;
    for (int i = tid; i < NT; i += 256) { float v = p[i]; buf[i] = v; m = fmaxf(m, v); }
    red[tid] = m; __syncthreads();
    for (int s = 128; s; s >>= 1) { if (tid < s) red[tid] = fmaxf(red[tid], red[tid+s]); __syncthreads(); }
    m = red[0]; __syncthreads();
    float sum = 0.f;
    for (int i = tid; i < NT; i += 256) { float e = __expf(buf[i] - m); buf[i] = e; sum += e; }
    red[tid] = sum; __syncthreads();
    for (int s = 128; s; s >>= 1) { if (tid < s) red[tid] += red[tid+s]; __syncthreads(); }
    float inv = 1.0f / red[0];
    for (int i = tid; i < NT; i += 256) p[i] = buf[i] * inv;
}

// ---------------- attn @ V -> zcat, per (b,dir): 1600x256x1600 ----------------
__global__ void av_gemm() {
    int m0 = blockIdx.x * 64, n0 = blockIdx.y * 64;
    int dir = blockIdx.z >> 3, b = blockIdx.z & 7;
    const float* P = (dir ? g_attn1 : g_attn0) + (size_t)b * NT * NT + (size_t)m0 * NT;
    const float* V = g_tok[dir ? 5 : 2] + (size_t)b * NT * Cc + n0;   // [k][n] layout
    float* out = g_zcat + (size_t)b * NT * 2 * Cc + (size_t)m0 * 2 * Cc + dir * Cc + n0;
    gemm_tile64<true, false>(P, NT, V, Cc, out, 2 * Cc, nullptr, 1.0f, NT);
}

// ---------------- epilogue GEMMs: h_rgb, h_ir (K=256), gate (K=512) ----------------
__global__ void final_gemm(const float* __restrict__ Wrgb, const float* __restrict__ brgb,
                           const float* __restrict__ Wir,  const float* __restrict__ bir,
                           const float* __restrict__ Wz,   const float* __restrict__ bz) {
    int m0 = blockIdx.x * 64, n0 = blockIdx.y * 64, jj = blockIdx.z;
    const float* A = g_zcat + (size_t)m0 * 2 * Cc + (jj == 1 ? Cc : 0);
    int Kd = (jj == 2) ? 2 * Cc : Cc;
    const float* W    = (jj == 0) ? Wrgb : ((jj == 1) ? Wir : Wz);
    const float* bias = (jj == 0) ? brgb : ((jj == 1) ? bir : bz);
    gemm_tile64<false, true>(A, 2 * Cc, W + (size_t)n0 * Kd, Kd,
                             g_pre[jj] + (size_t)m0 * Cc + n0, Cc, bias + n0, 1.0f, Kd);
}

// ---------------- gate fuse + transpose to [B,C,N] ----------------
__global__ void fuse_kernel(const int* __restrict__ time_idx, const float* __restrict__ temb) {
    int idx = blockIdx.x * blockDim.x + threadIdx.x;
    if (idx >= MT * Cc) return;
    int c = idx % Cc;
    int rem = idx / Cc;       // b*NT + n
    int n = rem % NT, b = rem / NT;
    float hr = tanhf(g_pre[0][idx]);
    float hi = tanhf(g_pre[1][idx]);
    float zb = 1.0f / (1.0f + __expf(-g_pre[2][idx]));
    float t  = temb[time_idx[b] * Cc + c];
    float z  = 1.0f / (1.0f + __expf(-(zb + t)));
    g_fused[(b * Cc + c) * NT + n] = z * hr + (1.0f - z) * hi;
}

// ---------------- bilinear upsample 40 -> 160 ----------------
__global__ void upsample_kernel(float* __restrict__ out) {
    int idx = blockIdx.x * blockDim.x + threadIdx.x;
    if (idx >= Bb*Cc*HH*WW) return;
    int w  = idx % WW;
    int h  = (idx / WW) % HH;
    int bc = idx / (HH * WW);
    float sh = fmaxf(h * 0.25f - 0.375f, 0.0f);
    float sw = fmaxf(w * 0.25f - 0.375f, 0.0f);
    int h0 = (int)sh; float fh = sh - (float)h0; int h1 = min(h0 + 1, HDs - 1);
    int w0 = (int)sw; float fw = sw - (float)w0; int w1 = min(w0 + 1, WDs - 1);
    const float* p = g_fused + bc * NT;
    float v00 = p[h0 * WDs + w0], v01 = p[h0 * WDs + w1];
    float v10 = p[h1 * WDs + w0], v11 = p[h1 * WDs + w1];
    float top = v00 * (1.0f - fw) + v01 * fw;
    float bot = v10 * (1.0f - fw) + v11 * fw;
    out[idx] = top * (1.0f - fh) + bot * fh;
}

extern "C" void kernel_launch(void* const* d_in, const int* in_sizes, int n_in,
                              void* d_out, int out_size) {
    const float* z_rgb  = (const float*)d_in[0];
    const float* z_ir   = (const float*)d_in[1];
    const int*   tidx   = (const int*)  d_in[2];
    const float* Wq_rgb = (const float*)d_in[3],  *bq_rgb = (const float*)d_in[4];
    const float* Wk_ir  = (const float*)d_in[5],  *bk_ir  = (const float*)d_in[6];
    const float* Wv_ir  = (const float*)d_in[7],  *bv_ir  = (const float*)d_in[8];
    const float* Wq_ir  = (const float*)d_in[9],  *bq_ir  = (const float*)d_in[10];
    const float* Wk_rgb = (const float*)d_in[11], *bk_rgb = (const float*)d_in[12];
    const float* Wv_rgb = (const float*)d_in[13], *bv_rgb = (const float*)d_in[14];
    const float* Wrgb   = (const float*)d_in[15], *brgb   = (const float*)d_in[16];
    const float* Wir    = (const float*)d_in[17], *bir    = (const float*)d_in[18];
    const float* Wz     = (const float*)d_in[19], *bz     = (const float*)d_in[20];
    const float* temb   = (const float*)d_in[21];

    ds_kernel<<<(MT*Cc + 255) / 256, 256>>>(z_rgb, z_ir);
    proj_gemm<<<dim3(200, 4, 6), 128>>>(Wq_rgb, bq_rgb, Wk_ir, bk_ir, Wv_ir, bv_ir,
                                        Wq_ir, bq_ir, Wk_rgb, bk_rgb, Wv_rgb, bv_rgb);
    scores_gemm<<<dim3(25, 25, 16), 128>>>();
    softmax_kernel<<<dim3(NT, 16), 256>>>();
    av_gemm<<<dim3(25, 4, 16), 128>>>();
    final_gemm<<<dim3(200, 4, 3), 128>>>(Wrgb, brgb, Wir, bir, Wz, bz);
    fuse_kernel<<<(MT*Cc + 255) / 256, 256>>>(tidx, temb);
    upsample_kernel<<<(Bb*Cc*HH*WW + 255) / 256, 256>>>((float*)d_out);
}

// round 3
// speedup vs baseline: 3.3270x; 1.1865x over previous
#include <cuda_runtime.h>
#include <math.h>
#include <float.h>

#define Bb  8
#define Cc  256
#define HH  160
#define WW  160
#define HDs 40
#define WDs 40
#define NT  1600            // tokens per batch
#define MT  (Bb*NT)         // 12800 total tokens
#define PAD 36              // smem row stride (floats)
#define NBLK 25             // column blocks per attention row (1600/64)

// ---------------- static scratch ----------------
__device__ float g_ds_rgb[MT*Cc];            // [B,C,N] (n fastest)
__device__ float g_ds_ir [MT*Cc];
__device__ float g_tok[6][MT*Cc];            // [B*N, C] token-major
__device__ float g_attn0[(size_t)Bb*NT*NT];  // exp(scores) rgb->ir
__device__ float g_attn1[(size_t)Bb*NT*NT];  // exp(scores) ir->rgb
__device__ float g_psum[2*Bb*NT*NBLK];       // per-row partial expsums
__device__ float g_rowinv[2*Bb*NT];          // 1/rowsum
__device__ float g_zcat[MT*2*Cc];            // [B*N, 2C]
__device__ float g_pre[3][MT*Cc];            // pre-activation h_rgb, h_ir, gate
__device__ float g_fused[Bb*Cc*NT];          // [B,C,N]

__device__ __forceinline__ unsigned f2tf(float x) {
    unsigned r; asm("cvt.rna.tf32.f32 %0, %1;" : "=r"(r) : "f"(x)); return r;
}

// ---------------- double-buffered tf32 mainloop: 64x64 tile, 128 threads ----------------
// A_KM:  A stored [k][m] (lda between k rows) ; else [m][k]
// B_KN:  B stored [k][n] (ldb between k rows) ; else [n][k]
template<bool A_KM, bool B_KN>
__device__ __forceinline__ void gemm_mainloop(
    const float* __restrict__ A, int lda,
    const float* __restrict__ B, int ldb,
    int K, float acc[2][4][4], unsigned* As, unsigned* Bs)
{
    const int tid = threadIdx.x;
    const int lane = tid & 31, warp = tid >> 5;
    const int wm = (warp >> 1) * 32, wn = (warp & 1) * 32;
    const int g = lane >> 2, tg = lane & 3;

    float4 ra[4], rb[4];

    auto loadT = [&](int k0) {
#pragma unroll
        for (int i = 0; i < 4; i++) {
            int idx = tid + i * 128;
            if (A_KM) { int k = idx >> 4, mg = (idx & 15) * 4;
                ra[i] = *(const float4*)(A + (size_t)(k0 + k) * lda + mg);
            } else {    int m = idx >> 3, kg = (idx & 7) * 4;
                ra[i] = *(const float4*)(A + (size_t)m * lda + k0 + kg);
            }
            if (B_KN) { int k = idx >> 4, ng = (idx & 15) * 4;
                rb[i] = *(const float4*)(B + (size_t)(k0 + k) * ldb + ng);
            } else {    int n = idx >> 3, kg = (idx & 7) * 4;
                rb[i] = *(const float4*)(B + (size_t)n * ldb + k0 + kg);
            }
        }
    };
    auto storeT = [&](unsigned* sa, unsigned* sb) {
#pragma unroll
        for (int i = 0; i < 4; i++) {
            int idx = tid + i * 128;
            if (A_KM) { int k = idx >> 4, mg = (idx & 15) * 4;
                sa[(mg+0)*PAD + k] = f2tf(ra[i].x); sa[(mg+1)*PAD + k] = f2tf(ra[i].y);
                sa[(mg+2)*PAD + k] = f2tf(ra[i].z); sa[(mg+3)*PAD + k] = f2tf(ra[i].w);
            } else {    int m = idx >> 3, kg = (idx & 7) * 4; unsigned* p = &sa[m*PAD + kg];
                p[0] = f2tf(ra[i].x); p[1] = f2tf(ra[i].y);
                p[2] = f2tf(ra[i].z); p[3] = f2tf(ra[i].w);
            }
            if (B_KN) { int k = idx >> 4, ng = (idx & 15) * 4;
                sb[(ng+0)*PAD + k] = f2tf(rb[i].x); sb[(ng+1)*PAD + k] = f2tf(rb[i].y);
                sb[(ng+2)*PAD + k] = f2tf(rb[i].z); sb[(ng+3)*PAD + k] = f2tf(rb[i].w);
            } else {    int n = idx >> 3, kg = (idx & 7) * 4; unsigned* p = &sb[n*PAD + kg];
                p[0] = f2tf(rb[i].x); p[1] = f2tf(rb[i].y);
                p[2] = f2tf(rb[i].z); p[3] = f2tf(rb[i].w);
            }
        }
    };
    auto compute = [&](const unsigned* sa, const unsigned* sb) {
#pragma unroll
        for (int s = 0; s < 4; s++) {
            const int kk = s * 8;
            unsigned a[2][4], b[4][2];
#pragma unroll
            for (int mi = 0; mi < 2; mi++) {
                int rm = wm + mi * 16;
                a[mi][0] = sa[(rm + g) * PAD + kk + tg];
                a[mi][1] = sa[(rm + 8 + g) * PAD + kk + tg];
                a[mi][2] = sa[(rm + g) * PAD + kk + tg + 4];
                a[mi][3] = sa[(rm + 8 + g) * PAD + kk + tg + 4];
            }
#pragma unroll
            for (int ni = 0; ni < 4; ni++) {
                int rn = wn + ni * 8;
                b[ni][0] = sb[(rn + g) * PAD + kk + tg];
                b[ni][1] = sb[(rn + g) * PAD + kk + tg + 4];
            }
#pragma unroll
            for (int mi = 0; mi < 2; mi++)
#pragma unroll
                for (int ni = 0; ni < 4; ni++) {
                    asm volatile(
                        "mma.sync.aligned.m16n8k8.row.col.f32.tf32.tf32.f32 "
                        "{%0,%1,%2,%3}, {%4,%5,%6,%7}, {%8,%9}, {%0,%1,%2,%3};"
                        : "+f"(acc[mi][ni][0]), "+f"(acc[mi][ni][1]),
                          "+f"(acc[mi][ni][2]), "+f"(acc[mi][ni][3])
                        : "r"(a[mi][0]), "r"(a[mi][1]), "r"(a[mi][2]), "r"(a[mi][3]),
                          "r"(b[ni][0]), "r"(b[ni][1]));
                }
        }
    };

    loadT(0);
    storeT(As, Bs);
    __syncthreads();
    int buf = 0;
    for (int k0 = 0; k0 < K; k0 += 32) {
        bool nxt = (k0 + 32 < K);
        if (nxt) loadT(k0 + 32);
        compute(As + buf * 64 * PAD, Bs + buf * 64 * PAD);
        if (nxt) {
            storeT(As + (buf ^ 1) * 64 * PAD, Bs + (buf ^ 1) * 64 * PAD);
            __syncthreads();
            buf ^= 1;
        }
    }
}

// ---------------- downsample: exact 2x2 mean -> [B,C,N] (n fastest) ----------------
__global__ void ds_kernel(const float* __restrict__ zr, const float* __restrict__ zi) {
    int idx = blockIdx.x * blockDim.x + threadIdx.x;
    if (idx >= MT * Cc) return;
    int n = idx % NT, bc = idx / NT;
    int ho = n / WDs, wo = n % WDs;
    int base = (bc * HH + 4 * ho + 1) * WW + 4 * wo + 1;
    g_ds_rgb[idx] = 0.25f * (zr[base] + zr[base+1] + zr[base+WW] + zr[base+WW+1]);
    g_ds_ir [idx] = 0.25f * (zi[base] + zi[base+1] + zi[base+WW] + zi[base+WW+1]);
}

// ---------------- projections: 6 GEMMs, M=12800 (A in [k][m]), N=256, K=256 ----------------
__global__ void proj_gemm(
    const float* __restrict__ Wq_rgb, const float* __restrict__ bq_rgb,
    const float* __restrict__ Wk_ir,  const float* __restrict__ bk_ir,
    const float* __restrict__ Wv_ir,  const float* __restrict__ bv_ir,
    const float* __restrict__ Wq_ir,  const float* __restrict__ bq_ir,
    const float* __restrict__ Wk_rgb, const float* __restrict__ bk_rgb,
    const float* __restrict__ Wv_rgb, const float* __restrict__ bv_rgb)
{
    __shared__ unsigned As[2*64*PAD];
    __shared__ unsigned Bs[2*64*PAD];
    int m0 = blockIdx.x * 64, n0 = blockIdx.y * 64, p = blockIdx.z;
    const float *Ain, *W, *bias;
    switch (p) {
        case 0: Ain = g_ds_rgb; W = Wq_rgb; bias = bq_rgb; break;
        case 1: Ain = g_ds_ir;  W = Wk_ir;  bias = bk_ir;  break;
        case 2: Ain = g_ds_ir;  W = Wv_ir;  bias = bv_ir;  break;
        case 3: Ain = g_ds_ir;  W = Wq_ir;  bias = bq_ir;  break;
        case 4: Ain = g_ds_rgb; W = Wk_rgb; bias = bk_rgb; break;
        default:Ain = g_ds_rgb; W = Wv_rgb; bias = bv_rgb; break;
    }
    int b = m0 / NT, nloc = m0 % NT;
    const float* A = Ain + (size_t)b * Cc * NT + nloc;
    float acc[2][4][4] = {};
    gemm_mainloop<true, false>(A, NT, W + (size_t)n0 * Cc, Cc, Cc, acc, As, Bs);

    const int tid = threadIdx.x, lane = tid & 31, warp = tid >> 5;
    const int wm = (warp >> 1) * 32, wn = (warp & 1) * 32;
    const int g = lane >> 2, tg = lane & 3;
    float* out = g_tok[p] + (size_t)m0 * Cc + n0;
#pragma unroll
    for (int mi = 0; mi < 2; mi++)
#pragma unroll
        for (int ni = 0; ni < 4; ni++) {
            int col = wn + ni * 8 + 2 * tg;
            float b0 = bias[n0 + col], b1 = bias[n0 + col + 1];
            int r0 = wm + mi * 16 + g;
            float2 v0 = { acc[mi][ni][0] + b0, acc[mi][ni][1] + b1 };
            float2 v1 = { acc[mi][ni][2] + b0, acc[mi][ni][3] + b1 };
            *(float2*)(out + (size_t)r0 * Cc + col) = v0;
            *(float2*)(out + (size_t)(r0 + 8) * Cc + col) = v1;
        }
}

// ---------------- scores: attn = exp((Q K^T)/16), plus per-row partial sums ----------------
__global__ void scores_gemm() {
    __shared__ unsigned As[2*64*PAD];
    __shared__ unsigned Bs[2*64*PAD];
    __shared__ float rsum[64];
    int m0 = blockIdx.x * 64, n0 = blockIdx.y * 64;
    int z = blockIdx.z;                     // dir*8 + b
    int dir = z >> 3, b = z & 7;
    const float* Aq = g_tok[dir ? 3 : 0] + (size_t)b * NT * Cc + (size_t)m0 * Cc;
    const float* Bk = g_tok[dir ? 4 : 1] + (size_t)b * NT * Cc + (size_t)n0 * Cc;
    float* out = (dir ? g_attn1 : g_attn0) + (size_t)b * NT * NT + (size_t)m0 * NT + n0;

    if (threadIdx.x < 64) rsum[threadIdx.x] = 0.f;
    float acc[2][4][4] = {};
    gemm_mainloop<false, false>(Aq, Cc, Bk, Cc, Cc, acc, As, Bs);
    __syncthreads();   // rsum init visible (also after mainloop's last compute)

    const int tid = threadIdx.x, lane = tid & 31, warp = tid >> 5;
    const int wm = (warp >> 1) * 32, wn = (warp & 1) * 32;
    const int g = lane >> 2, tg = lane & 3;
#pragma unroll
    for (int mi = 0; mi < 2; mi++) {
        float p0 = 0.f, p1 = 0.f;
#pragma unroll
        for (int ni = 0; ni < 4; ni++) {
            int col = wn + ni * 8 + 2 * tg;
            float e0 = __expf(acc[mi][ni][0] * 0.0625f);
            float e1 = __expf(acc[mi][ni][1] * 0.0625f);
            float e2 = __expf(acc[mi][ni][2] * 0.0625f);
            float e3 = __expf(acc[mi][ni][3] * 0.0625f);
            int r0 = wm + mi * 16 + g;
            *(float2*)(out + (size_t)r0 * NT + col) = make_float2(e0, e1);
            *(float2*)(out + (size_t)(r0 + 8) * NT + col) = make_float2(e2, e3);
            p0 += e0 + e1;
            p1 += e2 + e3;
        }
        // reduce across the 4 tg lanes (same g)
        p0 += __shfl_xor_sync(0xffffffffu, p0, 1); p0 += __shfl_xor_sync(0xffffffffu, p0, 2);
        p1 += __shfl_xor_sync(0xffffffffu, p1, 1); p1 += __shfl_xor_sync(0xffffffffu, p1, 2);
        if (tg == 0) {
            atomicAdd(&rsum[wm + mi * 16 + g], p0);       // 2 commutative adds per slot
            atomicAdd(&rsum[wm + mi * 16 + 8 + g], p1);
        }
    }
    __syncthreads();
    if (tid < 64)
        g_psum[((size_t)z * NT + m0 + tid) * NBLK + blockIdx.y] = rsum[tid];
}

// ---------------- rowsum reduce: 1/sum of 25 partials ----------------
__global__ void rowinv_kernel() {
    int idx = blockIdx.x * blockDim.x + threadIdx.x;
    if (idx >= 2 * Bb * NT) return;
    float s = 0.f;
    const float* p = g_psum + (size_t)idx * NBLK;
#pragma unroll
    for (int j = 0; j < NBLK; j++) s += p[j];
    g_rowinv[idx] = 1.0f / s;
}

// ---------------- attn @ V, normalized by rowsum -> zcat ----------------
__global__ void av_gemm() {
    __shared__ unsigned As[2*64*PAD];
    __shared__ unsigned Bs[2*64*PAD];
    int m0 = blockIdx.x * 64, n0 = blockIdx.y * 64;
    int z = blockIdx.z;
    int dir = z >> 3, b = z & 7;
    const float* P = (dir ? g_attn1 : g_attn0) + (size_t)b * NT * NT + (size_t)m0 * NT;
    const float* V = g_tok[dir ? 5 : 2] + (size_t)b * NT * Cc + n0;
    float* out = g_zcat + (size_t)b * NT * 2 * Cc + (size_t)m0 * 2 * Cc + dir * Cc + n0;
    const float* rinv = g_rowinv + (size_t)z * NT + m0;

    float acc[2][4][4] = {};
    gemm_mainloop<false, true>(P, NT, V, Cc, NT, acc, As, Bs);

    const int tid = threadIdx.x, lane = tid & 31, warp = tid >> 5;
    const int wm = (warp >> 1) * 32, wn = (warp & 1) * 32;
    const int g = lane >> 2, tg = lane & 3;
#pragma unroll
    for (int mi = 0; mi < 2; mi++) {
        int r0 = wm + mi * 16 + g;
        float i0 = rinv[r0], i1 = rinv[r0 + 8];
#pragma unroll
        for (int ni = 0; ni < 4; ni++) {
            int col = wn + ni * 8 + 2 * tg;
            float2 v0 = { acc[mi][ni][0] * i0, acc[mi][ni][1] * i0 };
            float2 v1 = { acc[mi][ni][2] * i1, acc[mi][ni][3] * i1 };
            *(float2*)(out + (size_t)r0 * 2 * Cc + col) = v0;
            *(float2*)(out + (size_t)(r0 + 8) * 2 * Cc + col) = v1;
        }
    }
}

// ---------------- epilogue GEMMs: h_rgb, h_ir (K=256), gate (K=512) ----------------
__global__ void final_gemm(const float* __restrict__ Wrgb, const float* __restrict__ brgb,
                           const float* __restrict__ Wir,  const float* __restrict__ bir,
                           const float* __restrict__ Wz,   const float* __restrict__ bz) {
    __shared__ unsigned As[2*64*PAD];
    __shared__ unsigned Bs[2*64*PAD];
    int m0 = blockIdx.x * 64, n0 = blockIdx.y * 64, jj = blockIdx.z;
    const float* A = g_zcat + (size_t)m0 * 2 * Cc + (jj == 1 ? Cc : 0);
    int Kd = (jj == 2) ? 2 * Cc : Cc;
    const float* W    = (jj == 0) ? Wrgb : ((jj == 1) ? Wir : Wz);
    const float* bias = (jj == 0) ? brgb : ((jj == 1) ? bir : bz);
    float acc[2][4][4] = {};
    gemm_mainloop<false, false>(A, 2 * Cc, W + (size_t)n0 * Kd, Kd, Kd, acc, As, Bs);

    const int tid = threadIdx.x, lane = tid & 31, warp = tid >> 5;
    const int wm = (warp >> 1) * 32, wn = (warp & 1) * 32;
    const int g = lane >> 2, tg = lane & 3;
    float* out = g_pre[jj] + (size_t)m0 * Cc + n0;
#pragma unroll
    for (int mi = 0; mi < 2; mi++)
#pragma unroll
        for (int ni = 0; ni < 4; ni++) {
            int col = wn + ni * 8 + 2 * tg;
            float b0 = bias[n0 + col], b1 = bias[n0 + col + 1];
            int r0 = wm + mi * 16 + g;
            float2 v0 = { acc[mi][ni][0] + b0, acc[mi][ni][1] + b1 };
            float2 v1 = { acc[mi][ni][2] + b0, acc[mi][ni][3] + b1 };
            *(float2*)(out + (size_t)r0 * Cc + col) = v0;
            *(float2*)(out + (size_t)(r0 + 8) * Cc + col) = v1;
        }
}

// ---------------- gate fuse + smem transpose to [B,C,N] ----------------
__global__ void fuse_kernel(const int* __restrict__ time_idx, const float* __restrict__ temb) {
    __shared__ float t[32][33];
    int b = blockIdx.z;
    int n0 = blockIdx.x * 32, c0 = blockIdx.y * 32;
    int tx = threadIdx.x, ty = threadIdx.y;
    int ti = time_idx[b];
#pragma unroll
    for (int i = 0; i < 4; i++) {
        int n = n0 + ty + 8 * i, c = c0 + tx;
        size_t m = ((size_t)b * NT + n) * Cc + c;
        float hr = tanhf(g_pre[0][m]);
        float hi = tanhf(g_pre[1][m]);
        float zb = 1.0f / (1.0f + __expf(-g_pre[2][m]));
        float te = temb[ti * Cc + c];
        float zf = 1.0f / (1.0f + __expf(-(zb + te)));
        t[ty + 8 * i][tx] = zf * hr + (1.0f - zf) * hi;
    }
    __syncthreads();
#pragma unroll
    for (int i = 0; i < 4; i++) {
        int c = c0 + ty + 8 * i, n = n0 + tx;
        g_fused[((size_t)b * Cc + c) * NT + n] = t[tx][ty + 8 * i];
    }
}

// ---------------- bilinear upsample 40 -> 160 ----------------
__global__ void upsample_kernel(float* __restrict__ out) {
    int idx = blockIdx.x * blockDim.x + threadIdx.x;
    if (idx >= Bb*Cc*HH*WW) return;
    int w  = idx % WW;
    int h  = (idx / WW) % HH;
    int bc = idx / (HH * WW);
    float sh = fmaxf(h * 0.25f - 0.375f, 0.0f);
    float sw = fmaxf(w * 0.25f - 0.375f, 0.0f);
    int h0 = (int)sh; float fh = sh - (float)h0; int h1 = min(h0 + 1, HDs - 1);
    int w0 = (int)sw; float fw = sw - (float)w0; int w1 = min(w0 + 1, WDs - 1);
    const float* p = g_fused + (size_t)bc * NT;
    float v00 = p[h0 * WDs + w0], v01 = p[h0 * WDs + w1];
    float v10 = p[h1 * WDs + w0], v11 = p[h1 * WDs + w1];
    float top = v00 * (1.0f - fw) + v01 * fw;
    float bot = v10 * (1.0f - fw) + v11 * fw;
    out[idx] = top * (1.0f - fh) + bot * fh;
}

extern "C" void kernel_launch(void* const* d_in, const int* in_sizes, int n_in,
                              void* d_out, int out_size) {
    const float* z_rgb  = (const float*)d_in[0];
    const float* z_ir   = (const float*)d_in[1];
    const int*   tidx   = (const int*)  d_in[2];
    const float* Wq_rgb = (const float*)d_in[3],  *bq_rgb = (const float*)d_in[4];
    const float* Wk_ir  = (const float*)d_in[5],  *bk_ir  = (const float*)d_in[6];
    const float* Wv_ir  = (const float*)d_in[7],  *bv_ir  = (const float*)d_in[8];
    const float* Wq_ir  = (const float*)d_in[9],  *bq_ir  = (const float*)d_in[10];
    const float* Wk_rgb = (const float*)d_in[11], *bk_rgb = (const float*)d_in[12];
    const float* Wv_rgb = (const float*)d_in[13], *bv_rgb = (const float*)d_in[14];
    const float* Wrgb   = (const float*)d_in[15], *brgb   = (const float*)d_in[16];
    const float* Wir    = (const float*)d_in[17], *bir    = (const float*)d_in[18];
    const float* Wz     = (const float*)d_in[19], *bz     = (const float*)d_in[20];
    const float* temb   = (const float*)d_in[21];

    ds_kernel<<<(MT*Cc + 255) / 256, 256>>>(z_rgb, z_ir);
    proj_gemm<<<dim3(200, 4, 6), 128>>>(Wq_rgb, bq_rgb, Wk_ir, bk_ir, Wv_ir, bv_ir,
                                        Wq_ir, bq_ir, Wk_rgb, bk_rgb, Wv_rgb, bv_rgb);
    scores_gemm<<<dim3(25, 25, 16), 128>>>();
    rowinv_kernel<<<(2*Bb*NT + 255) / 256, 256>>>();
    av_gemm<<<dim3(25, 4, 16), 128>>>();
    final_gemm<<<dim3(200, 4, 3), 128>>>(Wrgb, brgb, Wir, bir, Wz, bz);
    fuse_kernel<<<dim3(NT/32, Cc/32, Bb), dim3(32, 8)>>>(tidx, temb);
    upsample_kernel<<<(Bb*Cc*HH*WW + 255) / 256, 256>>>((float*)d_out);
}

// round 4
// speedup vs baseline: 5.0557x; 1.5196x over previous
#include <cuda_runtime.h>
#include <math.h>
#include <float.h>
#include <stdint.h>

#define Bb  8
#define Cc  256
#define HH  160
#define WW  160
#define HDs 40
#define WDs 40
#define NT  1600            // tokens per batch
#define MT  (Bb*NT)         // 12800 total tokens
#define ATW 1664            // padded attention width (13 * 128)
#define NBLK 13             // n-tiles per attention row
#define A_SZ 2304           // A tile words (64*36 or 32*72)
#define B_SZ 4608           // B tile words (128*36; B_tr 32*136=4352 fits)
#define SMEM_BYTES ((2*A_SZ + 2*B_SZ) * 4)

// ---------------- static scratch ----------------
__device__ float g_ds_rgb[MT*Cc];                 // [B,C,N] tf32-rounded
__device__ float g_ds_ir [MT*Cc];
__device__ float g_tok[6][MT*Cc + 64*Cc];         // [B*N, C] tf32-rounded (+zero tail)
__device__ float g_attn0[(size_t)Bb*NT*ATW];      // exp(scores) rgb->ir, tf32, pad cols = 0
__device__ float g_attn1[(size_t)Bb*NT*ATW];
__device__ float g_psum[2*Bb*NT*NBLK];
__device__ float g_rowinv[2*Bb*NT];
__device__ float g_zcat[MT*2*Cc];                 // [B*N, 2C] tf32-rounded
__device__ float g_pre[3][MT*Cc];                 // f32 pre-activations
__device__ float g_fused[Bb*Cc*NT];               // [B,C,N]
__device__ float g_w[655360];                     // tf32-rounded weights

__device__ __forceinline__ unsigned f2tf(float x) {
    unsigned r; asm("cvt.rna.tf32.f32 %0, %1;" : "=r"(r) : "f"(x)); return r;
}
__device__ __forceinline__ float f2tff(float x) { return __uint_as_float(f2tf(x)); }

__device__ __forceinline__ void cpa16(const float* smem_dst, const float* gsrc) {
    uint32_t s = (uint32_t)__cvta_generic_to_shared(smem_dst);
    asm volatile("cp.async.cg.shared.global [%0], [%1], 16;" :: "r"(s), "l"(gsrc));
}

// ---------------- tf32 GEMM core: 64(M) x 128(N) block, 4 warps, warp tile 32x64 ----
// AT: 0 = A stored [m][k] (lda), 1 = A stored [k][m] (lda)
// BT: 0 = B stored [n][k] (ldb), 1 = B stored [k][n] (ldb)
template<int AT, int BT>
__device__ __forceinline__ void gemm_core(
    const float* __restrict__ A, int lda,
    const float* __restrict__ B, int ldb,
    int K, float acc[2][8][4], float* sm)
{
    float* As0 = sm;            float* As1 = sm + A_SZ;
    float* Bs0 = sm + 2*A_SZ;   float* Bs1 = sm + 2*A_SZ + B_SZ;
    const int tid = threadIdx.x, lane = tid & 31, warp = tid >> 5;
    const int wm = (warp >> 1) * 32, wn = (warp & 1) * 64;
    const int g = lane >> 2, tg = lane & 3;

    auto issue = [&](int k0, int bufi) {
        float* as = bufi ? As1 : As0;
        float* bs = bufi ? Bs1 : Bs0;
#pragma unroll
        for (int i = 0; i < 4; i++) {
            int idx = tid + i * 128;
            if (AT == 0) { int m = idx >> 3, kg = (idx & 7) * 4;
                cpa16(as + m * 36 + kg, A + (size_t)m * lda + k0 + kg);
            } else {       int k = idx >> 4, mg = (idx & 15) * 4;
                cpa16(as + k * 72 + mg, A + (size_t)(k0 + k) * lda + mg);
            }
        }
#pragma unroll
        for (int i = 0; i < 8; i++) {
            int idx = tid + i * 128;
            if (BT == 0) { int n = idx >> 3, kg = (idx & 7) * 4;
                cpa16(bs + n * 36 + kg, B + (size_t)n * ldb + k0 + kg);
            } else {       int k = idx >> 5, ng = (idx & 31) * 4;
                cpa16(bs + k * 136 + ng, B + (size_t)(k0 + k) * ldb + ng);
            }
        }
        asm volatile("cp.async.commit_group;");
    };

    issue(0, 0);
    int buf = 0;
    for (int k0 = 0; k0 < K; k0 += 32) {
        asm volatile("cp.async.wait_group 0;");
        __syncthreads();
        if (k0 + 32 < K) issue(k0 + 32, buf ^ 1);
        const float* as = buf ? As1 : As0;
        const float* bs = buf ? Bs1 : Bs0;
#pragma unroll
        for (int s = 0; s < 4; s++) {
            const int kk = s * 8;
            unsigned a[2][4], b[8][2];
#pragma unroll
            for (int mi = 0; mi < 2; mi++) {
                int r = wm + mi * 16 + g;
                if (AT == 0) {
                    a[mi][0] = __float_as_uint(as[r * 36 + kk + tg]);
                    a[mi][1] = __float_as_uint(as[(r + 8) * 36 + kk + tg]);
                    a[mi][2] = __float_as_uint(as[r * 36 + kk + tg + 4]);
                    a[mi][3] = __float_as_uint(as[(r + 8) * 36 + kk + tg + 4]);
                } else {
                    a[mi][0] = __float_as_uint(as[(kk + tg) * 72 + r]);
                    a[mi][1] = __float_as_uint(as[(kk + tg) * 72 + r + 8]);
                    a[mi][2] = __float_as_uint(as[(kk + tg + 4) * 72 + r]);
                    a[mi][3] = __float_as_uint(as[(kk + tg + 4) * 72 + r + 8]);
                }
            }
#pragma unroll
            for (int ni = 0; ni < 8; ni++) {
                int n = wn + ni * 8 + g;
                if (BT == 0) {
                    b[ni][0] = __float_as_uint(bs[n * 36 + kk + tg]);
                    b[ni][1] = __float_as_uint(bs[n * 36 + kk + tg + 4]);
                } else {
                    b[ni][0] = __float_as_uint(bs[(kk + tg) * 136 + n]);
                    b[ni][1] = __float_as_uint(bs[(kk + tg + 4) * 136 + n]);
                }
            }
#pragma unroll
            for (int mi = 0; mi < 2; mi++)
#pragma unroll
                for (int ni = 0; ni < 8; ni++) {
                    asm volatile(
                        "mma.sync.aligned.m16n8k8.row.col.f32.tf32.tf32.f32 "
                        "{%0,%1,%2,%3}, {%4,%5,%6,%7}, {%8,%9}, {%0,%1,%2,%3};"
                        : "+f"(acc[mi][ni][0]), "+f"(acc[mi][ni][1]),
                          "+f"(acc[mi][ni][2]), "+f"(acc[mi][ni][3])
                        : "r"(a[mi][0]), "r"(a[mi][1]), "r"(a[mi][2]), "r"(a[mi][3]),
                          "r"(b[ni][0]), "r"(b[ni][1]));
                }
        }
        buf ^= 1;
    }
}

// ---------------- weight prep: tf32-round all 9 weight matrices ----------------
__global__ void wprep_kernel(
    const float* w0, const float* w1, const float* w2, const float* w3,
    const float* w4, const float* w5, const float* w6, const float* w7,
    const float* w8)
{
    int seg = blockIdx.y;
    int idx = blockIdx.x * 256 + threadIdx.x;
    int size = (seg == 8) ? 131072 : 65536;
    if (idx >= size) return;
    const float* src;
    switch (seg) {
        case 0: src = w0; break; case 1: src = w1; break; case 2: src = w2; break;
        case 3: src = w3; break; case 4: src = w4; break; case 5: src = w5; break;
        case 6: src = w6; break; case 7: src = w7; break; default: src = w8; break;
    }
    g_w[seg * 65536 + idx] = f2tff(src[idx]);
}

// ---------------- downsample: exact 2x2 mean -> [B,C,N], tf32-rounded ----------------
__global__ void ds_kernel(const float* __restrict__ zr, const float* __restrict__ zi) {
    int idx = blockIdx.x * blockDim.x + threadIdx.x;
    if (idx >= MT * Cc) return;
    int n = idx % NT, bc = idx / NT;
    int ho = n / WDs, wo = n % WDs;
    int base = (bc * HH + 4 * ho + 1) * WW + 4 * wo + 1;
    g_ds_rgb[idx] = f2tff(0.25f * (zr[base] + zr[base+1] + zr[base+WW] + zr[base+WW+1]));
    g_ds_ir [idx] = f2tff(0.25f * (zi[base] + zi[base+1] + zi[base+WW] + zi[base+WW+1]));
}

// ---------------- projections: A = ds [k][m] per batch, B = W[n][k] ----------------
__global__ void proj_gemm(
    const float* __restrict__ bq_rgb, const float* __restrict__ bk_ir,
    const float* __restrict__ bv_ir,  const float* __restrict__ bq_ir,
    const float* __restrict__ bk_rgb, const float* __restrict__ bv_rgb)
{
    extern __shared__ float sm[];
    int m0 = blockIdx.x * 64, n0 = blockIdx.y * 128, p = blockIdx.z;
    const float* Ain = (p == 0 || p == 4 || p == 5) ? g_ds_rgb : g_ds_ir;
    const float* bias;
    switch (p) {
        case 0: bias = bq_rgb; break; case 1: bias = bk_ir;  break;
        case 2: bias = bv_ir;  break; case 3: bias = bq_ir;  break;
        case 4: bias = bk_rgb; break; default: bias = bv_rgb; break;
    }
    int b = m0 / NT, nloc = m0 % NT;
    const float* A = Ain + (size_t)b * Cc * NT + nloc;
    const float* W = g_w + p * 65536 + (size_t)n0 * Cc;

    float acc[2][8][4] = {};
    gemm_core<1, 0>(A, NT, W, Cc, Cc, acc, sm);

    const int tid = threadIdx.x, lane = tid & 31, warp = tid >> 5;
    const int wm = (warp >> 1) * 32, wn = (warp & 1) * 64;
    const int g = lane >> 2, tg = lane & 3;
    float* out = g_tok[p];
#pragma unroll
    for (int mi = 0; mi < 2; mi++) {
        int r0 = m0 + wm + mi * 16 + g;
#pragma unroll
        for (int ni = 0; ni < 8; ni++) {
            int col = n0 + wn + ni * 8 + 2 * tg;
            float b0 = bias[col], b1 = bias[col + 1];
            float2 v0 = { f2tff(acc[mi][ni][0] + b0), f2tff(acc[mi][ni][1] + b1) };
            float2 v1 = { f2tff(acc[mi][ni][2] + b0), f2tff(acc[mi][ni][3] + b1) };
            *(float2*)(out + (size_t)r0 * Cc + col) = v0;
            *(float2*)(out + (size_t)(r0 + 8) * Cc + col) = v1;
        }
    }
}

// ---------------- scores: attn = exp((Q K^T)/16) (pad cols 0), partial rowsums ------
__global__ void scores_gemm() {
    extern __shared__ float sm[];
    __shared__ float rsum[64];
    int m0 = blockIdx.x * 64, n0 = blockIdx.y * 128;
    int z = blockIdx.z, dir = z >> 3, b = z & 7;
    const float* Aq = g_tok[dir ? 3 : 0] + (size_t)b * NT * Cc + (size_t)m0 * Cc;
    const float* Bk = g_tok[dir ? 4 : 1] + (size_t)b * NT * Cc + (size_t)n0 * Cc;
    float* out = (dir ? g_attn1 : g_attn0) + (size_t)b * NT * ATW + (size_t)m0 * ATW + n0;

    if (threadIdx.x < 64) rsum[threadIdx.x] = 0.f;
    float acc[2][8][4] = {};
    gemm_core<0, 0>(Aq, Cc, Bk, Cc, Cc, acc, sm);

    const int tid = threadIdx.x, lane = tid & 31, warp = tid >> 5;
    const int wm = (warp >> 1) * 32, wn = (warp & 1) * 64;
    const int g = lane >> 2, tg = lane & 3;
#pragma unroll
    for (int mi = 0; mi < 2; mi++) {
        int r0 = wm + mi * 16 + g;
        float p0 = 0.f, p1 = 0.f;
#pragma unroll
        for (int ni = 0; ni < 8; ni++) {
            int col = wn + ni * 8 + 2 * tg;
            bool real = (n0 + col) < NT;
            float e0 = real ? __expf(acc[mi][ni][0] * 0.0625f) : 0.f;
            float e1 = real ? __expf(acc[mi][ni][1] * 0.0625f) : 0.f;
            float e2 = real ? __expf(acc[mi][ni][2] * 0.0625f) : 0.f;
            float e3 = real ? __expf(acc[mi][ni][3] * 0.0625f) : 0.f;
            *(float2*)(out + (size_t)r0 * ATW + col) =
                make_float2(__uint_as_float(f2tf(e0)), __uint_as_float(f2tf(e1)));
            *(float2*)(out + (size_t)(r0 + 8) * ATW + col) =
                make_float2(__uint_as_float(f2tf(e2)), __uint_as_float(f2tf(e3)));
            p0 += e0 + e1;
            p1 += e2 + e3;
        }
        p0 += __shfl_xor_sync(0xffffffffu, p0, 1); p0 += __shfl_xor_sync(0xffffffffu, p0, 2);
        p1 += __shfl_xor_sync(0xffffffffu, p1, 1); p1 += __shfl_xor_sync(0xffffffffu, p1, 2);
        if (tg == 0) {
            atomicAdd(&rsum[r0], p0);
            atomicAdd(&rsum[r0 + 8], p1);
        }
    }
    __syncthreads();
    if (tid < 64)
        g_psum[((size_t)z * NT + m0 + tid) * NBLK + blockIdx.y] = rsum[tid];
}

// ---------------- rowsum reduce ----------------
__global__ void rowinv_kernel() {
    int idx = blockIdx.x * blockDim.x + threadIdx.x;
    if (idx >= 2 * Bb * NT) return;
    float s = 0.f;
    const float* p = g_psum + (size_t)idx * NBLK;
#pragma unroll
    for (int j = 0; j < NBLK; j++) s += p[j];
    g_rowinv[idx] = 1.0f / s;
}

// ---------------- attn @ V (K=1664, pad contributes 0), normalized -> zcat ----------
__global__ void av_gemm() {
    extern __shared__ float sm[];
    int m0 = blockIdx.x * 64, n0 = blockIdx.y * 128;
    int z = blockIdx.z, dir = z >> 3, b = z & 7;
    const float* P = (dir ? g_attn1 : g_attn0) + (size_t)b * NT * ATW + (size_t)m0 * ATW;
    const float* V = g_tok[dir ? 5 : 2] + (size_t)b * NT * Cc + n0;
    float* out = g_zcat + (size_t)b * NT * 2 * Cc + (size_t)m0 * 2 * Cc + dir * Cc + n0;
    const float* rinv = g_rowinv + (size_t)z * NT + m0;

    float acc[2][8][4] = {};
    gemm_core<0, 1>(P, ATW, V, Cc, ATW, acc, sm);

    const int tid = threadIdx.x, lane = tid & 31, warp = tid >> 5;
    const int wm = (warp >> 1) * 32, wn = (warp & 1) * 64;
    const int g = lane >> 2, tg = lane & 3;
#pragma unroll
    for (int mi = 0; mi < 2; mi++) {
        int r0 = wm + mi * 16 + g;
        float i0 = rinv[r0], i1 = rinv[r0 + 8];
#pragma unroll
        for (int ni = 0; ni < 8; ni++) {
            int col = wn + ni * 8 + 2 * tg;
            float2 v0 = { f2tff(acc[mi][ni][0] * i0), f2tff(acc[mi][ni][1] * i0) };
            float2 v1 = { f2tff(acc[mi][ni][2] * i1), f2tff(acc[mi][ni][3] * i1) };
            *(float2*)(out + (size_t)r0 * 2 * Cc + col) = v0;
            *(float2*)(out + (size_t)(r0 + 8) * 2 * Cc + col) = v1;
        }
    }
}

// ---------------- epilogue GEMMs ----------------
__global__ void final_gemm(const float* __restrict__ brgb, const float* __restrict__ bir,
                           const float* __restrict__ bz) {
    extern __shared__ float sm[];
    int m0 = blockIdx.x * 64, n0 = blockIdx.y * 128, jj = blockIdx.z;
    const float* A = g_zcat + (size_t)m0 * 2 * Cc + (jj == 1 ? Cc : 0);
    int Kd = (jj == 2) ? 2 * Cc : Cc;
    const float* W    = (jj == 2) ? (g_w + 524288) : (g_w + (6 + jj) * 65536);
    const float* bias = (jj == 0) ? brgb : ((jj == 1) ? bir : bz);

    float acc[2][8][4] = {};
    gemm_core<0, 0>(A, 2 * Cc, W + (size_t)n0 * Kd, Kd, Kd, acc, sm);

    const int tid = threadIdx.x, lane = tid & 31, warp = tid >> 5;
    const int wm = (warp >> 1) * 32, wn = (warp & 1) * 64;
    const int g = lane >> 2, tg = lane & 3;
    float* out = g_pre[jj] + (size_t)m0 * Cc + n0;
#pragma unroll
    for (int mi = 0; mi < 2; mi++) {
        int r0 = wm + mi * 16 + g;
#pragma unroll
        for (int ni = 0; ni < 8; ni++) {
            int col = wn + ni * 8 + 2 * tg;
            float b0 = bias[n0 + col], b1 = bias[n0 + col + 1];
            float2 v0 = { acc[mi][ni][0] + b0, acc[mi][ni][1] + b1 };
            float2 v1 = { acc[mi][ni][2] + b0, acc[mi][ni][3] + b1 };
            *(float2*)(out + (size_t)r0 * Cc + col) = v0;
            *(float2*)(out + (size_t)(r0 + 8) * Cc + col) = v1;
        }
    }
}

// ---------------- gate fuse + smem transpose to [B,C,N] ----------------
__global__ void fuse_kernel(const int* __restrict__ time_idx, const float* __restrict__ temb) {
    __shared__ float t[32][33];
    int b = blockIdx.z;
    int n0 = blockIdx.x * 32, c0 = blockIdx.y * 32;
    int tx = threadIdx.x, ty = threadIdx.y;
    int ti = time_idx[b];
#pragma unroll
    for (int i = 0; i < 4; i++) {
        int n = n0 + ty + 8 * i, c = c0 + tx;
        size_t m = ((size_t)b * NT + n) * Cc + c;
        float hr = tanhf(g_pre[0][m]);
        float hi = tanhf(g_pre[1][m]);
        float zb = 1.0f / (1.0f + __expf(-g_pre[2][m]));
        float te = temb[ti * Cc + c];
        float zf = 1.0f / (1.0f + __expf(-(zb + te)));
        t[ty + 8 * i][tx] = zf * hr + (1.0f - zf) * hi;
    }
    __syncthreads();
#pragma unroll
    for (int i = 0; i < 4; i++) {
        int c = c0 + ty + 8 * i, n = n0 + tx;
        g_fused[((size_t)b * Cc + c) * NT + n] = t[tx][ty + 8 * i];
    }
}

// ---------------- bilinear upsample 40 -> 160 ----------------
__global__ void upsample_kernel(float* __restrict__ out) {
    int idx = blockIdx.x * blockDim.x + threadIdx.x;
    if (idx >= Bb*Cc*HH*WW) return;
    int w  = idx % WW;
    int h  = (idx / WW) % HH;
    int bc = idx / (HH * WW);
    float sh = fmaxf(h * 0.25f - 0.375f, 0.0f);
    float sw = fmaxf(w * 0.25f - 0.375f, 0.0f);
    int h0 = (int)sh; float fh = sh - (float)h0; int h1 = min(h0 + 1, HDs - 1);
    int w0 = (int)sw; float fw = sw - (float)w0; int w1 = min(w0 + 1, WDs - 1);
    const float* p = g_fused + (size_t)bc * NT;
    float v00 = p[h0 * WDs + w0], v01 = p[h0 * WDs + w1];
    float v10 = p[h1 * WDs + w0], v11 = p[h1 * WDs + w1];
    float top = v00 * (1.0f - fw) + v01 * fw;
    float bot = v10 * (1.0f - fw) + v11 * fw;
    out[idx] = top * (1.0f - fh) + bot * fh;
}

extern "C" void kernel_launch(void* const* d_in, const int* in_sizes, int n_in,
                              void* d_out, int out_size) {
    const float* z_rgb  = (const float*)d_in[0];
    const float* z_ir   = (const float*)d_in[1];
    const int*   tidx   = (const int*)  d_in[2];
    const float* Wq_rgb = (const float*)d_in[3],  *bq_rgb = (const float*)d_in[4];
    const float* Wk_ir  = (const float*)d_in[5],  *bk_ir  = (const float*)d_in[6];
    const float* Wv_ir  = (const float*)d_in[7],  *bv_ir  = (const float*)d_in[8];
    const float* Wq_ir  = (const float*)d_in[9],  *bq_ir  = (const float*)d_in[10];
    const float* Wk_rgb = (const float*)d_in[11], *bk_rgb = (const float*)d_in[12];
    const float* Wv_rgb = (const float*)d_in[13], *bv_rgb = (const float*)d_in[14];
    const float* Wrgb   = (const float*)d_in[15], *brgb   = (const float*)d_in[16];
    const float* Wir    = (const float*)d_in[17], *bir    = (const float*)d_in[18];
    const float* Wz     = (const float*)d_in[19], *bz     = (const float*)d_in[20];
    const float* temb   = (const float*)d_in[21];

    static bool attr_done = false;
    if (!attr_done) {
        cudaFuncSetAttribute(proj_gemm,  cudaFuncAttributeMaxDynamicSharedMemorySize, SMEM_BYTES);
        cudaFuncSetAttribute(scores_gemm, cudaFuncAttributeMaxDynamicSharedMemorySize, SMEM_BYTES);
        cudaFuncSetAttribute(av_gemm,    cudaFuncAttributeMaxDynamicSharedMemorySize, SMEM_BYTES);
        cudaFuncSetAttribute(final_gemm, cudaFuncAttributeMaxDynamicSharedMemorySize, SMEM_BYTES);
        attr_done = true;
    }

    wprep_kernel<<<dim3(512, 9), 256>>>(Wq_rgb, Wk_ir, Wv_ir, Wq_ir, Wk_rgb, Wv_rgb,
                                        Wrgb, Wir, Wz);
    ds_kernel<<<(MT*Cc + 255) / 256, 256>>>(z_rgb, z_ir);
    proj_gemm<<<dim3(200, 2, 6), 128, SMEM_BYTES>>>(bq_rgb, bk_ir, bv_ir, bq_ir, bk_rgb, bv_rgb);
    scores_gemm<<<dim3(25, NBLK, 16), 128, SMEM_BYTES>>>();
    rowinv_kernel<<<(2*Bb*NT + 255) / 256, 256>>>();
    av_gemm<<<dim3(25, 2, 16), 128, SMEM_BYTES>>>();
    final_gemm<<<dim3(200, 2, 3), 128, SMEM_BYTES>>>(brgb, bir, bz);
    fuse_kernel<<<dim3(NT/32, Cc/32, Bb), dim3(32, 8)>>>(tidx, temb);
    upsample_kernel<<<(Bb*Cc*HH*WW + 255) / 256, 256>>>((float*)d_out);
}